// round 5
// baseline (speedup 1.0000x reference)
#include <cuda_runtime.h>
#include <cuda_bf16.h>
#include <cstdint>

// ============================================================
// FP8ProperLinear: out = fq(x) @ fq(w)^T + bias
//   fq = per-tensor fake e4m3 quantize (values have <=4-bit significands)
// Exactness: quantize in scaled space -> bf16 (exact), bf16 products are
// exact, fp32 accumulate; fold amax_x*amax_w/448^2 + bias into epilogue.
// GEMM core: mma.sync m16n8k16 bf16, warp tile 64x64, CTA tile 128x256,
// fragment double-buffering across k16 steps (hide LDSM latency).
// (tcgen05 unavailable: harness PTX target is plain sm_103.)
// ============================================================

static constexpr int M = 8192;     // B*S
static constexpr int N = 16384;    // OUT_F
static constexpr int K = 4096;     // IN_F

static constexpr int BM = 128, BN = 256, BK = 64;
static constexpr int STAGES = 4;
static constexpr int KSTAGES = K / BK;            // 64
static constexpr int GROUP_M = 8;

static constexpr uint32_t STG_A = BM * BK * 2;    // 16384 B
static constexpr uint32_t STG_B = BN * BK * 2;    // 32768 B
static constexpr uint32_t SM_A = 0;
static constexpr uint32_t SM_B = STAGES * STG_A;  // 65536
static constexpr uint32_t SMEM_BYTES = SM_B + STAGES * STG_B;  // 196608

// ---------------- device scratch (no mallocs allowed) ----------------
__device__ __nv_bfloat16 g_xq[(size_t)M * K];   // 64 MiB
__device__ __nv_bfloat16 g_wq[(size_t)N * K];   // 128 MiB
__device__ unsigned g_amax[2];                  // [0]=x, [1]=w (float bits)

// ---------------- helpers ----------------
__device__ __forceinline__ uint32_t smem_u32(const void* p) {
    uint32_t a;
    asm("{ .reg .u64 t; cvta.to.shared.u64 t, %1; cvt.u32.u64 %0, t; }" : "=r"(a) : "l"(p));
    return a;
}
__device__ __forceinline__ uint32_t sw128(uint32_t off) {   // SW128 XOR swizzle
    return off ^ ((off >> 3) & 0x70);
}
__device__ __forceinline__ void cpa16(uint32_t dst, const void* src) {
    asm volatile("cp.async.cg.shared.global [%0], [%1], 16;" :: "r"(dst), "l"(src));
}
#define CP_COMMIT() asm volatile("cp.async.commit_group;" ::: "memory")
#define CP_WAIT2()  asm volatile("cp.async.wait_group 2;" ::: "memory")

__device__ __forceinline__ void ldsm_x4(uint32_t& r0, uint32_t& r1, uint32_t& r2,
                                        uint32_t& r3, uint32_t addr) {
    asm volatile("ldmatrix.sync.aligned.m8n8.x4.shared.b16 {%0,%1,%2,%3}, [%4];"
                 : "=r"(r0), "=r"(r1), "=r"(r2), "=r"(r3) : "r"(addr));
}
__device__ __forceinline__ void mma16816(float* c, const uint32_t* a, const uint32_t* b) {
    asm volatile("mma.sync.aligned.m16n8k16.row.col.f32.bf16.bf16.f32 "
                 "{%0,%1,%2,%3}, {%4,%5,%6,%7}, {%8,%9}, {%0,%1,%2,%3};"
                 : "+f"(c[0]), "+f"(c[1]), "+f"(c[2]), "+f"(c[3])
                 : "r"(a[0]), "r"(a[1]), "r"(a[2]), "r"(a[3]), "r"(b[0]), "r"(b[1]));
}

// ---------------- fake e4m3 quantize (scaled space; exact exponent) ----------------
__device__ __forceinline__ float fq_scaled(float v, float scale) {
    float c = fminf(fmaxf(v, -448.f), 448.f);
    float s = c * scale;
    float mag = fmaxf(fabsf(s), 1e-12f);                 // always normal
    uint32_t e = (__float_as_uint(mag) >> 23) & 0xFFu;   // biased exponent
    float step = __uint_as_float((e - 3u) << 23);        // 2^(e-127)/8 (exact)
    float inv  = __uint_as_float((257u - e) << 23);      // 1/step      (exact)
    float r = rintf(mag * inv);                          // round-half-even
    float q = r * step;                                  // <=5 sig bits: exact
    return (s > 0.f) ? q : ((s < 0.f) ? -q : 0.f);
}

// ---------------- pre-GEMM kernels ----------------
__global__ void k_init() { g_amax[0] = 0u; g_amax[1] = 0u; }

__global__ void k_amax(const float* __restrict__ p, int n4, int which) {
    __shared__ float red[32];
    float m = 0.f;
    int stride = gridDim.x * blockDim.x;
    const float4* p4 = (const float4*)p;
    for (int i = blockIdx.x * blockDim.x + threadIdx.x; i < n4; i += stride) {
        float4 v = p4[i];
        m = fmaxf(m, fmaxf(fmaxf(fabsf(v.x), fabsf(v.y)), fmaxf(fabsf(v.z), fabsf(v.w))));
    }
    #pragma unroll
    for (int o = 16; o; o >>= 1) m = fmaxf(m, __shfl_xor_sync(0xffffffffu, m, o));
    if ((threadIdx.x & 31) == 0) red[threadIdx.x >> 5] = m;
    __syncthreads();
    if (threadIdx.x < 32) {
        float t = (threadIdx.x < (blockDim.x >> 5)) ? red[threadIdx.x] : 0.f;
        #pragma unroll
        for (int o = 16; o; o >>= 1) t = fmaxf(t, __shfl_xor_sync(0xffffffffu, t, o));
        if (threadIdx.x == 0) {
            t = fminf(t, 448.f);  // amax of clamped tensor
            atomicMax(&g_amax[which], __float_as_uint(t));
        }
    }
}

__global__ void k_quant(const float* __restrict__ in, int n4, int which) {
    __nv_bfloat16* out = which ? g_wq : g_xq;
    float amax = fmaxf(__uint_as_float(g_amax[which]), 1e-12f);
    float scale = 448.f / amax;
    int stride = gridDim.x * blockDim.x;
    const float4* p4 = (const float4*)in;
    uint2* o4 = (uint2*)out;
    for (int i = blockIdx.x * blockDim.x + threadIdx.x; i < n4; i += stride) {
        float4 v = p4[i];
        unsigned short b0 = __bfloat16_as_ushort(__float2bfloat16(fq_scaled(v.x, scale)));
        unsigned short b1 = __bfloat16_as_ushort(__float2bfloat16(fq_scaled(v.y, scale)));
        unsigned short b2 = __bfloat16_as_ushort(__float2bfloat16(fq_scaled(v.z, scale)));
        unsigned short b3 = __bfloat16_as_ushort(__float2bfloat16(fq_scaled(v.w, scale)));
        uint2 r;
        r.x = (uint32_t)b0 | ((uint32_t)b1 << 16);
        r.y = (uint32_t)b2 | ((uint32_t)b3 << 16);
        o4[i] = r;
    }
}

// ---------------- GEMM: out = (xq @ wq^T) * oscale + bias ----------------
__global__ void __launch_bounds__(256, 1)
k_gemm(const float* __restrict__ bias, float* __restrict__ out) {
    extern __shared__ __align__(128) char smem[];
    const uint32_t base = smem_u32(smem);
    const int tid  = threadIdx.x;
    const int wid  = tid >> 5, lane = tid & 31;
    const int wm   = wid & 1;      // 2 warps along M: rows wm*64..+63
    const int wn   = wid >> 1;     // 4 warps along N: cols wn*64..+63

    // grouped raster
    const int num_pid_n = N / BN;                 // 64
    int pid = blockIdx.x;
    int group_sz = GROUP_M * num_pid_n;           // 512
    int g = pid / group_sz;
    int pin = pid - g * group_sz;
    int bm = g * GROUP_M + (pin % GROUP_M);
    int bn = pin / GROUP_M;

    const char* Abase = (const char*)(g_xq + (size_t)bm * BM * K);
    const char* Bbase = (const char*)(g_wq + (size_t)bn * BN * K);

    // ---- stage loader: A 128x64 bf16 (16KB), B 256x64 bf16 (32KB), SW128 ----
    auto load_stage = [&](int s) {
        int buf = s & (STAGES - 1);
        const char* A = Abase + (size_t)s * BK * 2;
        const char* B = Bbase + (size_t)s * BK * 2;
        uint32_t sa = base + SM_A + buf * STG_A;
        uint32_t sb = base + SM_B + buf * STG_B;
        #pragma unroll
        for (int i = 0; i < 4; i++) {            // A: 1024 16B chunks
            int idx = tid + i * 256;
            int row = idx >> 3, c = idx & 7;
            uint32_t off = (uint32_t)row * 128 + (uint32_t)c * 16;
            cpa16(sa + sw128(off), A + (size_t)row * (K * 2) + c * 16);
        }
        #pragma unroll
        for (int i = 0; i < 8; i++) {            // B: 2048 16B chunks
            int idx = tid + i * 256;
            int row = idx >> 3, c = idx & 7;
            uint32_t off = (uint32_t)row * 128 + (uint32_t)c * 16;
            cpa16(sb + sw128(off), B + (size_t)row * (K * 2) + c * 16);
        }
    };

    #pragma unroll
    for (int s = 0; s < STAGES - 1; s++) { load_stage(s); CP_COMMIT(); }

    // per-lane ldmatrix source rows
    int a_row_in16 = (lane & 7) + ((lane >> 3) & 1) * 8;
    int a_kh       = (lane >> 4);
    int b_row_in16 = (lane & 7) + ((lane >> 4) & 1) * 8;
    int b_kh       = (lane >> 3) & 1;

    // fragment fetch for one k16 step into the given buffers
    auto fetch_kk = [&](uint32_t sa, uint32_t sb, int kk,
                        uint32_t (*af)[4], uint32_t (*bfr)[4]) {
        #pragma unroll
        for (int mi = 0; mi < 4; mi++) {
            uint32_t row = (uint32_t)(wm * 64 + mi * 16 + a_row_in16);
            uint32_t off = row * 128 + (uint32_t)(kk * 2 + a_kh) * 16;
            ldsm_x4(af[mi][0], af[mi][1], af[mi][2], af[mi][3], sa + sw128(off));
        }
        #pragma unroll
        for (int nj = 0; nj < 4; nj++) {
            uint32_t row = (uint32_t)(wn * 64 + nj * 16 + b_row_in16);
            uint32_t off = row * 128 + (uint32_t)(kk * 2 + b_kh) * 16;
            ldsm_x4(bfr[nj][0], bfr[nj][1], bfr[nj][2], bfr[nj][3], sb + sw128(off));
        }
    };

    float acc[4][8][4];                          // 64x64 per warp
    #pragma unroll
    for (int i = 0; i < 4; i++)
        #pragma unroll
        for (int j = 0; j < 8; j++)
            #pragma unroll
            for (int q = 0; q < 4; q++) acc[i][j][q] = 0.f;

    uint32_t af[2][4][4], bf[2][4][4];           // double-buffered fragments

    for (int ks = 0; ks < KSTAGES; ks++) {
        int buf = ks & (STAGES - 1);
        CP_WAIT2();
        __syncthreads();

        uint32_t sa = base + SM_A + buf * STG_A;
        uint32_t sb = base + SM_B + buf * STG_B;

        // start first fragment fetch, THEN issue next stage's cp.asyncs so
        // LDSM latency and LDGSTS issue burst overlap.
        fetch_kk(sa, sb, 0, af[0], bf[0]);
        if (ks + STAGES - 1 < KSTAGES) load_stage(ks + STAGES - 1);
        CP_COMMIT();

        #pragma unroll
        for (int kk = 0; kk < BK / 16; kk++) {     // 4 k16 steps, pipelined
            int cur = kk & 1;
            if (kk < BK / 16 - 1)
                fetch_kk(sa, sb, kk + 1, af[cur ^ 1], bf[cur ^ 1]);
            #pragma unroll
            for (int mi = 0; mi < 4; mi++)
                #pragma unroll
                for (int nj = 0; nj < 4; nj++) {
                    mma16816(acc[mi][nj * 2 + 0], af[cur][mi], &bf[cur][nj][0]);
                    mma16816(acc[mi][nj * 2 + 1], af[cur][mi], &bf[cur][nj][2]);
                }
        }
    }

    // ---- epilogue: scale + bias, direct STG.64 ----
    float ax = fmaxf(__uint_as_float(g_amax[0]), 1e-12f);
    float aw = fmaxf(__uint_as_float(g_amax[1]), 1e-12f);
    float oscale = (ax * aw) * (1.f / (448.f * 448.f));

    int mrow0 = bm * BM + wm * 64 + (lane >> 2);
    int ncol0 = bn * BN + wn * 64 + (lane & 3) * 2;

    #pragma unroll
    for (int mi = 0; mi < 4; mi++) {
        #pragma unroll
        for (int j = 0; j < 8; j++) {
            int ncol = ncol0 + j * 8;
            float2 bv = *(const float2*)&bias[ncol];
            int r0 = mrow0 + mi * 16;
            float2 v0, v1;
            v0.x = acc[mi][j][0] * oscale + bv.x;
            v0.y = acc[mi][j][1] * oscale + bv.y;
            v1.x = acc[mi][j][2] * oscale + bv.x;
            v1.y = acc[mi][j][3] * oscale + bv.y;
            *(float2*)&out[(size_t)r0 * N + ncol]       = v0;
            *(float2*)&out[(size_t)(r0 + 8) * N + ncol] = v1;
        }
    }
}

// ---------------- launch ----------------
extern "C" void kernel_launch(void* const* d_in, const int* in_sizes, int n_in,
                              void* d_out, int out_size) {
    const float* x    = (const float*)d_in[0];
    const float* w    = (const float*)d_in[1];
    const float* bias = (const float*)d_in[2];
    float* out = (float*)d_out;

    cudaFuncSetAttribute(k_gemm, cudaFuncAttributeMaxDynamicSharedMemorySize,
                         (int)SMEM_BYTES);

    k_init<<<1, 1>>>();
    k_amax<<<2048, 256>>>(x, (M * K) / 4, 0);
    k_amax<<<2048, 256>>>(w, (N * K) / 4, 1);
    k_quant<<<2048, 256>>>(x, (M * K) / 4, 0);
    k_quant<<<2048, 256>>>(w, (N * K) / 4, 1);

    int grid = (M / BM) * (N / BN);   // 64 * 64 = 4096
    k_gemm<<<grid, 256, SMEM_BYTES>>>(bias, out);
}

// round 6
// speedup vs baseline: 1.0804x; 1.0804x over previous
#include <cuda_runtime.h>
#include <cuda_bf16.h>
#include <cstdint>

// ============================================================
// FP8ProperLinear: out = fq(x) @ fq(w)^T + bias
//   fq = per-tensor fake e4m3 quantize (values have <=4-bit significands)
// Exactness: quantize in scaled space -> bf16 (exact), bf16 products are
// exact, fp32 accumulate; fold amax_x*amax_w/448^2 + bias into epilogue.
// GEMM core: mma.sync m16n8k16 bf16, CTA tile 128x128x64, warp tile 64x32,
// 3-stage cp.async pipeline, 2 CTAs/SM (independent CTAs overlap each
// other's sync windows, keeping the HMMA pipe fed).
// (tcgen05 unavailable: harness PTX target is plain sm_103.)
// ============================================================

static constexpr int M = 8192;     // B*S
static constexpr int N = 16384;    // OUT_F
static constexpr int K = 4096;     // IN_F

static constexpr int BM = 128, BN = 128, BK = 64;
static constexpr int STAGES = 3;
static constexpr int KSTAGES = K / BK;            // 64
static constexpr int GROUP_M = 8;

static constexpr uint32_t STG_A = BM * BK * 2;    // 16384 B
static constexpr uint32_t STG_B = BN * BK * 2;    // 16384 B
static constexpr uint32_t SM_A = 0;
static constexpr uint32_t SM_B = STAGES * STG_A;  // 49152
static constexpr uint32_t SMEM_BYTES = SM_B + STAGES * STG_B;  // 98304 (x2 CTAs = 192K)

// ---------------- device scratch (no mallocs allowed) ----------------
__device__ __nv_bfloat16 g_xq[(size_t)M * K];   // 64 MiB
__device__ __nv_bfloat16 g_wq[(size_t)N * K];   // 128 MiB
__device__ unsigned g_amax[2];                  // [0]=x, [1]=w (float bits)

// ---------------- helpers ----------------
__device__ __forceinline__ uint32_t smem_u32(const void* p) {
    uint32_t a;
    asm("{ .reg .u64 t; cvta.to.shared.u64 t, %1; cvt.u32.u64 %0, t; }" : "=r"(a) : "l"(p));
    return a;
}
__device__ __forceinline__ uint32_t sw128(uint32_t off) {   // SW128 XOR swizzle
    return off ^ ((off >> 3) & 0x70);
}
__device__ __forceinline__ void cpa16(uint32_t dst, const void* src) {
    asm volatile("cp.async.cg.shared.global [%0], [%1], 16;" :: "r"(dst), "l"(src));
}
#define CP_COMMIT() asm volatile("cp.async.commit_group;" ::: "memory")
#define CP_WAIT1()  asm volatile("cp.async.wait_group 1;" ::: "memory")

__device__ __forceinline__ void ldsm_x4(uint32_t& r0, uint32_t& r1, uint32_t& r2,
                                        uint32_t& r3, uint32_t addr) {
    asm volatile("ldmatrix.sync.aligned.m8n8.x4.shared.b16 {%0,%1,%2,%3}, [%4];"
                 : "=r"(r0), "=r"(r1), "=r"(r2), "=r"(r3) : "r"(addr));
}
__device__ __forceinline__ void mma16816(float* c, const uint32_t* a, const uint32_t* b) {
    asm volatile("mma.sync.aligned.m16n8k16.row.col.f32.bf16.bf16.f32 "
                 "{%0,%1,%2,%3}, {%4,%5,%6,%7}, {%8,%9}, {%0,%1,%2,%3};"
                 : "+f"(c[0]), "+f"(c[1]), "+f"(c[2]), "+f"(c[3])
                 : "r"(a[0]), "r"(a[1]), "r"(a[2]), "r"(a[3]), "r"(b[0]), "r"(b[1]));
}

// ---------------- fake e4m3 quantize (scaled space; exact exponent) ----------------
__device__ __forceinline__ float fq_scaled(float v, float scale) {
    float c = fminf(fmaxf(v, -448.f), 448.f);
    float s = c * scale;
    float mag = fmaxf(fabsf(s), 1e-12f);                 // always normal
    uint32_t e = (__float_as_uint(mag) >> 23) & 0xFFu;   // biased exponent
    float step = __uint_as_float((e - 3u) << 23);        // 2^(e-127)/8 (exact)
    float inv  = __uint_as_float((257u - e) << 23);      // 1/step      (exact)
    float r = rintf(mag * inv);                          // round-half-even
    float q = r * step;                                  // <=5 sig bits: exact
    return (s > 0.f) ? q : ((s < 0.f) ? -q : 0.f);
}

// ---------------- pre-GEMM kernels ----------------
__global__ void k_init() { g_amax[0] = 0u; g_amax[1] = 0u; }

__global__ void k_amax(const float* __restrict__ p, int n4, int which) {
    __shared__ float red[32];
    float m = 0.f;
    int stride = gridDim.x * blockDim.x;
    const float4* p4 = (const float4*)p;
    for (int i = blockIdx.x * blockDim.x + threadIdx.x; i < n4; i += stride) {
        float4 v = p4[i];
        m = fmaxf(m, fmaxf(fmaxf(fabsf(v.x), fabsf(v.y)), fmaxf(fabsf(v.z), fabsf(v.w))));
    }
    #pragma unroll
    for (int o = 16; o; o >>= 1) m = fmaxf(m, __shfl_xor_sync(0xffffffffu, m, o));
    if ((threadIdx.x & 31) == 0) red[threadIdx.x >> 5] = m;
    __syncthreads();
    if (threadIdx.x < 32) {
        float t = (threadIdx.x < (blockDim.x >> 5)) ? red[threadIdx.x] : 0.f;
        #pragma unroll
        for (int o = 16; o; o >>= 1) t = fmaxf(t, __shfl_xor_sync(0xffffffffu, t, o));
        if (threadIdx.x == 0) {
            t = fminf(t, 448.f);  // amax of clamped tensor
            atomicMax(&g_amax[which], __float_as_uint(t));
        }
    }
}

__global__ void k_quant(const float* __restrict__ in, int n4, int which) {
    __nv_bfloat16* out = which ? g_wq : g_xq;
    float amax = fmaxf(__uint_as_float(g_amax[which]), 1e-12f);
    float scale = 448.f / amax;
    int stride = gridDim.x * blockDim.x;
    const float4* p4 = (const float4*)in;
    uint2* o4 = (uint2*)out;
    for (int i = blockIdx.x * blockDim.x + threadIdx.x; i < n4; i += stride) {
        float4 v = p4[i];
        unsigned short b0 = __bfloat16_as_ushort(__float2bfloat16(fq_scaled(v.x, scale)));
        unsigned short b1 = __bfloat16_as_ushort(__float2bfloat16(fq_scaled(v.y, scale)));
        unsigned short b2 = __bfloat16_as_ushort(__float2bfloat16(fq_scaled(v.z, scale)));
        unsigned short b3 = __bfloat16_as_ushort(__float2bfloat16(fq_scaled(v.w, scale)));
        uint2 r;
        r.x = (uint32_t)b0 | ((uint32_t)b1 << 16);
        r.y = (uint32_t)b2 | ((uint32_t)b3 << 16);
        o4[i] = r;
    }
}

// ---------------- GEMM: out = (xq @ wq^T) * oscale + bias ----------------
__global__ void __launch_bounds__(256, 2)
k_gemm(const float* __restrict__ bias, float* __restrict__ out) {
    extern __shared__ __align__(128) char smem[];
    const uint32_t base = smem_u32(smem);
    const int tid  = threadIdx.x;
    const int wid  = tid >> 5, lane = tid & 31;
    const int wm   = wid & 1;      // 2 warps along M: rows wm*64..+63
    const int wn   = wid >> 1;     // 4 warps along N: cols wn*32..+31

    // grouped raster
    const int num_pid_n = N / BN;                 // 128
    int pid = blockIdx.x;
    int group_sz = GROUP_M * num_pid_n;           // 1024
    int g = pid / group_sz;
    int pin = pid - g * group_sz;
    int bm = g * GROUP_M + (pin % GROUP_M);
    int bn = pin / GROUP_M;

    const char* Abase = (const char*)(g_xq + (size_t)bm * BM * K);
    const char* Bbase = (const char*)(g_wq + (size_t)bn * BN * K);

    // ---- stage loader: A 128x64 bf16 (16KB), B 128x64 bf16 (16KB), SW128 ----
    auto load_stage = [&](int s) {
        int buf = s % STAGES;
        const char* A = Abase + (size_t)s * BK * 2;
        const char* B = Bbase + (size_t)s * BK * 2;
        uint32_t sa = base + SM_A + buf * STG_A;
        uint32_t sb = base + SM_B + buf * STG_B;
        #pragma unroll
        for (int i = 0; i < 4; i++) {            // A: 1024 16B chunks / 256 thr
            int idx = tid + i * 256;
            int row = idx >> 3, c = idx & 7;
            uint32_t off = (uint32_t)row * 128 + (uint32_t)c * 16;
            cpa16(sa + sw128(off), A + (size_t)row * (K * 2) + c * 16);
        }
        #pragma unroll
        for (int i = 0; i < 4; i++) {            // B: 1024 16B chunks
            int idx = tid + i * 256;
            int row = idx >> 3, c = idx & 7;
            uint32_t off = (uint32_t)row * 128 + (uint32_t)c * 16;
            cpa16(sb + sw128(off), B + (size_t)row * (K * 2) + c * 16);
        }
    };

    #pragma unroll
    for (int s = 0; s < STAGES - 1; s++) { load_stage(s); CP_COMMIT(); }

    // per-lane ldmatrix source rows
    // A x4: {m0-7@k0, m8-15@k0, m0-7@k8, m8-15@k8}
    int a_row_in16 = (lane & 7) + ((lane >> 3) & 1) * 8;
    int a_kh       = (lane >> 4);
    // B x4: {n0-7@k0, n0-7@k8, n8-15@k0, n8-15@k8}
    int b_row_in16 = (lane & 7) + ((lane >> 4) & 1) * 8;
    int b_kh       = (lane >> 3) & 1;

    float acc[4][4][4];                          // 64x32 per warp
    #pragma unroll
    for (int i = 0; i < 4; i++)
        #pragma unroll
        for (int j = 0; j < 4; j++)
            #pragma unroll
            for (int q = 0; q < 4; q++) acc[i][j][q] = 0.f;

    for (int ks = 0; ks < KSTAGES; ks++) {
        int buf = ks % STAGES;
        CP_WAIT1();
        __syncthreads();
        if (ks + STAGES - 1 < KSTAGES) load_stage(ks + STAGES - 1);
        CP_COMMIT();

        uint32_t sa = base + SM_A + buf * STG_A;
        uint32_t sb = base + SM_B + buf * STG_B;

        #pragma unroll
        for (int kk = 0; kk < BK / 16; kk++) {     // 4 k16 steps
            uint32_t af[4][4], bf[2][4];
            #pragma unroll
            for (int mi = 0; mi < 4; mi++) {
                uint32_t row = (uint32_t)(wm * 64 + mi * 16 + a_row_in16);
                uint32_t off = row * 128 + (uint32_t)(kk * 2 + a_kh) * 16;
                ldsm_x4(af[mi][0], af[mi][1], af[mi][2], af[mi][3],
                        sa + sw128(off));
            }
            #pragma unroll
            for (int nj = 0; nj < 2; nj++) {       // each covers n16 (2 frags)
                uint32_t row = (uint32_t)(wn * 32 + nj * 16 + b_row_in16);
                uint32_t off = row * 128 + (uint32_t)(kk * 2 + b_kh) * 16;
                ldsm_x4(bf[nj][0], bf[nj][1], bf[nj][2], bf[nj][3],
                        sb + sw128(off));
            }
            #pragma unroll
            for (int mi = 0; mi < 4; mi++)
                #pragma unroll
                for (int nj = 0; nj < 2; nj++) {
                    mma16816(acc[mi][nj * 2 + 0], af[mi], &bf[nj][0]);
                    mma16816(acc[mi][nj * 2 + 1], af[mi], &bf[nj][2]);
                }
        }
    }

    // ---- epilogue: scale + bias, direct STG.64 ----
    float ax = fmaxf(__uint_as_float(g_amax[0]), 1e-12f);
    float aw = fmaxf(__uint_as_float(g_amax[1]), 1e-12f);
    float oscale = (ax * aw) * (1.f / (448.f * 448.f));

    int mrow0 = bm * BM + wm * 64 + (lane >> 2);
    int ncol0 = bn * BN + wn * 32 + (lane & 3) * 2;

    #pragma unroll
    for (int mi = 0; mi < 4; mi++) {
        #pragma unroll
        for (int j = 0; j < 4; j++) {
            int ncol = ncol0 + j * 8;
            float2 bv = *(const float2*)&bias[ncol];
            int r0 = mrow0 + mi * 16;
            float2 v0, v1;
            v0.x = acc[mi][j][0] * oscale + bv.x;
            v0.y = acc[mi][j][1] * oscale + bv.y;
            v1.x = acc[mi][j][2] * oscale + bv.x;
            v1.y = acc[mi][j][3] * oscale + bv.y;
            *(float2*)&out[(size_t)r0 * N + ncol]       = v0;
            *(float2*)&out[(size_t)(r0 + 8) * N + ncol] = v1;
        }
    }
}

// ---------------- launch ----------------
extern "C" void kernel_launch(void* const* d_in, const int* in_sizes, int n_in,
                              void* d_out, int out_size) {
    const float* x    = (const float*)d_in[0];
    const float* w    = (const float*)d_in[1];
    const float* bias = (const float*)d_in[2];
    float* out = (float*)d_out;

    cudaFuncSetAttribute(k_gemm, cudaFuncAttributeMaxDynamicSharedMemorySize,
                         (int)SMEM_BYTES);

    k_init<<<1, 1>>>();
    k_amax<<<2048, 256>>>(x, (M * K) / 4, 0);
    k_amax<<<2048, 256>>>(w, (N * K) / 4, 1);
    k_quant<<<2048, 256>>>(x, (M * K) / 4, 0);
    k_quant<<<2048, 256>>>(w, (N * K) / 4, 1);

    int grid = (M / BM) * (N / BN);   // 64 * 128 = 8192
    k_gemm<<<grid, 256, SMEM_BYTES>>>(bias, out);
}

// round 7
// speedup vs baseline: 1.0844x; 1.0037x over previous
#include <cuda_runtime.h>
#include <cuda_bf16.h>
#include <cstdint>

// ============================================================
// FP8ProperLinear: out = fq(x) @ fq(w)^T + bias
//   fq = per-tensor fake e4m3 quantize (values have <=4-bit significands)
// Exactness: quantize in scaled space -> bf16 (exact), bf16 products are
// exact, fp32 accumulate; fold amax_x*amax_w/448^2 + bias into epilogue.
// GEMM core: mma.sync m16n8k16 bf16, CTA tile 128x128x64, warp tile 64x32,
// 3-stage cp.async pipeline, 2 CTAs/SM (independent CTAs overlap each
// other's sync windows, keeping the HMMA pipe fed).
// Pre-GEMM phase fused: one amax kernel (partials, no atomics/init),
// one scale kernel, one quant kernel covering both tensors.
// (tcgen05 unavailable: harness PTX target is plain sm_103.)
// ============================================================

static constexpr int M = 8192;     // B*S
static constexpr int N = 16384;    // OUT_F
static constexpr int K = 4096;     // IN_F

static constexpr int BM = 128, BN = 128, BK = 64;
static constexpr int STAGES = 3;
static constexpr int KSTAGES = K / BK;            // 64
static constexpr int GROUP_M = 8;

static constexpr uint32_t STG_A = BM * BK * 2;    // 16384 B
static constexpr uint32_t STG_B = BN * BK * 2;    // 16384 B
static constexpr uint32_t SM_A = 0;
static constexpr uint32_t SM_B = STAGES * STG_A;  // 49152
static constexpr uint32_t SMEM_BYTES = SM_B + STAGES * STG_B;  // 98304 (x2 CTAs = 192K)

// amax/quant grid split
static constexpr int AX_BLOCKS = 1024;            // x amax blocks
static constexpr int AW_BLOCKS = 2048;            // w amax blocks
static constexpr int QX_BLOCKS = 2048;            // x quant blocks
static constexpr int QW_BLOCKS = 4096;            // w quant blocks

// ---------------- device scratch (no mallocs allowed) ----------------
__device__ __nv_bfloat16 g_xq[(size_t)M * K];   // 64 MiB
__device__ __nv_bfloat16 g_wq[(size_t)N * K];   // 128 MiB
__device__ float g_part[AX_BLOCKS + AW_BLOCKS]; // per-block partial maxima
__device__ float g_scl[4];                      // [0]=scale_x [1]=scale_w [2]=amax_x [3]=amax_w

// ---------------- helpers ----------------
__device__ __forceinline__ uint32_t smem_u32(const void* p) {
    uint32_t a;
    asm("{ .reg .u64 t; cvta.to.shared.u64 t, %1; cvt.u32.u64 %0, t; }" : "=r"(a) : "l"(p));
    return a;
}
__device__ __forceinline__ uint32_t sw128(uint32_t off) {   // SW128 XOR swizzle
    return off ^ ((off >> 3) & 0x70);
}
__device__ __forceinline__ void cpa16(uint32_t dst, const void* src) {
    asm volatile("cp.async.cg.shared.global [%0], [%1], 16;" :: "r"(dst), "l"(src));
}
#define CP_COMMIT() asm volatile("cp.async.commit_group;" ::: "memory")
#define CP_WAIT1()  asm volatile("cp.async.wait_group 1;" ::: "memory")

__device__ __forceinline__ void ldsm_x4(uint32_t& r0, uint32_t& r1, uint32_t& r2,
                                        uint32_t& r3, uint32_t addr) {
    asm volatile("ldmatrix.sync.aligned.m8n8.x4.shared.b16 {%0,%1,%2,%3}, [%4];"
                 : "=r"(r0), "=r"(r1), "=r"(r2), "=r"(r3) : "r"(addr));
}
__device__ __forceinline__ void mma16816(float* c, const uint32_t* a, const uint32_t* b) {
    asm volatile("mma.sync.aligned.m16n8k16.row.col.f32.bf16.bf16.f32 "
                 "{%0,%1,%2,%3}, {%4,%5,%6,%7}, {%8,%9}, {%0,%1,%2,%3};"
                 : "+f"(c[0]), "+f"(c[1]), "+f"(c[2]), "+f"(c[3])
                 : "r"(a[0]), "r"(a[1]), "r"(a[2]), "r"(a[3]), "r"(b[0]), "r"(b[1]));
}

// ---------------- fake e4m3 quantize (scaled space; exact exponent) ----------------
__device__ __forceinline__ float fq_scaled(float v, float scale) {
    float c = fminf(fmaxf(v, -448.f), 448.f);
    float s = c * scale;
    float mag = fmaxf(fabsf(s), 1e-12f);                 // always normal
    uint32_t e = (__float_as_uint(mag) >> 23) & 0xFFu;   // biased exponent
    float step = __uint_as_float((e - 3u) << 23);        // 2^(e-127)/8 (exact)
    float inv  = __uint_as_float((257u - e) << 23);      // 1/step      (exact)
    float r = rintf(mag * inv);                          // round-half-even
    float q = r * step;                                  // <=5 sig bits: exact
    return (s > 0.f) ? q : ((s < 0.f) ? -q : 0.f);
}

// ---------------- pre-GEMM kernels ----------------
// One kernel covers both tensors: blocks [0, AX) -> x, [AX, AX+AW) -> w.
// Writes per-block partial max (all slots written every call: deterministic).
__global__ void __launch_bounds__(512)
k_amax_all(const float* __restrict__ x, const float* __restrict__ w) {
    __shared__ float red[16];
    int bid = blockIdx.x;
    const float4* p4;
    int n4, b0, nb;
    if (bid < AX_BLOCKS) { p4 = (const float4*)x; n4 = (M * K) / 4; b0 = bid;             nb = AX_BLOCKS; }
    else                 { p4 = (const float4*)w; n4 = (N * K) / 4; b0 = bid - AX_BLOCKS; nb = AW_BLOCKS; }

    float m0 = 0.f, m1 = 0.f;
    int stride = nb * 512 * 2;
    int i0 = (b0 * 512 + threadIdx.x) * 2;
    for (int i = i0; i < n4; i += stride) {
        float4 v = p4[i];
        m0 = fmaxf(m0, fmaxf(fmaxf(fabsf(v.x), fabsf(v.y)), fmaxf(fabsf(v.z), fabsf(v.w))));
        if (i + 1 < n4) {
            float4 u = p4[i + 1];
            m1 = fmaxf(m1, fmaxf(fmaxf(fabsf(u.x), fabsf(u.y)), fmaxf(fabsf(u.z), fabsf(u.w))));
        }
    }
    float m = fmaxf(m0, m1);
    #pragma unroll
    for (int o = 16; o; o >>= 1) m = fmaxf(m, __shfl_xor_sync(0xffffffffu, m, o));
    if ((threadIdx.x & 31) == 0) red[threadIdx.x >> 5] = m;
    __syncthreads();
    if (threadIdx.x < 32) {
        float t = (threadIdx.x < 16) ? red[threadIdx.x] : 0.f;
        #pragma unroll
        for (int o = 8; o; o >>= 1) t = fmaxf(t, __shfl_xor_sync(0xffffffffu, t, o));
        if (threadIdx.x == 0) g_part[bid] = fminf(t, 448.f);  // amax of clamped tensor
    }
}

// Reduce partials -> scales (1 block).
__global__ void __launch_bounds__(1024) k_scale() {
    __shared__ float red[32];
    int t = threadIdx.x;
    // x: partials [0, AX)
    float mx = (t < AX_BLOCKS) ? g_part[t] : 0.f;
    // w: partials [AX, AX+AW): each thread folds 2
    float mw = fmaxf(g_part[AX_BLOCKS + t], g_part[AX_BLOCKS + 1024 + t]);
    #pragma unroll
    for (int o = 16; o; o >>= 1) {
        mx = fmaxf(mx, __shfl_xor_sync(0xffffffffu, mx, o));
        mw = fmaxf(mw, __shfl_xor_sync(0xffffffffu, mw, o));
    }
    if ((t & 31) == 0) red[t >> 5] = mx;
    __syncthreads();
    if (t < 32) {
        float v = red[t];
        #pragma unroll
        for (int o = 16; o; o >>= 1) v = fmaxf(v, __shfl_xor_sync(0xffffffffu, v, o));
        if (t == 0) {
            float ax = fmaxf(v, 1e-12f);
            g_scl[0] = 448.f / ax;
            g_scl[2] = ax;
        }
    }
    __syncthreads();
    if ((t & 31) == 0) red[t >> 5] = mw;
    __syncthreads();
    if (t < 32) {
        float v = red[t];
        #pragma unroll
        for (int o = 16; o; o >>= 1) v = fmaxf(v, __shfl_xor_sync(0xffffffffu, v, o));
        if (t == 0) {
            float aw = fmaxf(v, 1e-12f);
            g_scl[1] = 448.f / aw;
            g_scl[3] = aw;
        }
    }
}

// One kernel quantizes both tensors: blocks [0, QX) -> x, rest -> w.
// 2 independent float4 chains per iteration for MLP.
__global__ void __launch_bounds__(256)
k_quant_all(const float* __restrict__ x, const float* __restrict__ w) {
    int bid = blockIdx.x;
    const float4* p4;
    uint2* o4;
    float scale;
    int n4, b0, nb;
    if (bid < QX_BLOCKS) {
        p4 = (const float4*)x; o4 = (uint2*)g_xq; scale = g_scl[0];
        n4 = (M * K) / 4; b0 = bid; nb = QX_BLOCKS;
    } else {
        p4 = (const float4*)w; o4 = (uint2*)g_wq; scale = g_scl[1];
        n4 = (N * K) / 4; b0 = bid - QX_BLOCKS; nb = QW_BLOCKS;
    }
    int stride = nb * 256 * 2;
    int i0 = (b0 * 256 + threadIdx.x) * 2;
    for (int i = i0; i < n4; i += stride) {
        float4 v = p4[i];
        bool has2 = (i + 1) < n4;
        float4 u = has2 ? p4[i + 1] : v;
        unsigned short b0s = __bfloat16_as_ushort(__float2bfloat16(fq_scaled(v.x, scale)));
        unsigned short b1s = __bfloat16_as_ushort(__float2bfloat16(fq_scaled(v.y, scale)));
        unsigned short b2s = __bfloat16_as_ushort(__float2bfloat16(fq_scaled(v.z, scale)));
        unsigned short b3s = __bfloat16_as_ushort(__float2bfloat16(fq_scaled(v.w, scale)));
        uint2 r;
        r.x = (uint32_t)b0s | ((uint32_t)b1s << 16);
        r.y = (uint32_t)b2s | ((uint32_t)b3s << 16);
        o4[i] = r;
        if (has2) {
            unsigned short c0 = __bfloat16_as_ushort(__float2bfloat16(fq_scaled(u.x, scale)));
            unsigned short c1 = __bfloat16_as_ushort(__float2bfloat16(fq_scaled(u.y, scale)));
            unsigned short c2 = __bfloat16_as_ushort(__float2bfloat16(fq_scaled(u.z, scale)));
            unsigned short c3 = __bfloat16_as_ushort(__float2bfloat16(fq_scaled(u.w, scale)));
            uint2 r2;
            r2.x = (uint32_t)c0 | ((uint32_t)c1 << 16);
            r2.y = (uint32_t)c2 | ((uint32_t)c3 << 16);
            o4[i + 1] = r2;
        }
    }
}

// ---------------- GEMM: out = (xq @ wq^T) * oscale + bias ----------------
__global__ void __launch_bounds__(256, 2)
k_gemm(const float* __restrict__ bias, float* __restrict__ out) {
    extern __shared__ __align__(128) char smem[];
    const uint32_t base = smem_u32(smem);
    const int tid  = threadIdx.x;
    const int wid  = tid >> 5, lane = tid & 31;
    const int wm   = wid & 1;      // 2 warps along M: rows wm*64..+63
    const int wn   = wid >> 1;     // 4 warps along N: cols wn*32..+31

    // grouped raster
    const int num_pid_n = N / BN;                 // 128
    int pid = blockIdx.x;
    int group_sz = GROUP_M * num_pid_n;           // 1024
    int g = pid / group_sz;
    int pin = pid - g * group_sz;
    int bm = g * GROUP_M + (pin % GROUP_M);
    int bn = pin / GROUP_M;

    const char* Abase = (const char*)(g_xq + (size_t)bm * BM * K);
    const char* Bbase = (const char*)(g_wq + (size_t)bn * BN * K);

    // ---- stage loader: A 128x64 bf16 (16KB), B 128x64 bf16 (16KB), SW128 ----
    auto load_stage = [&](int s) {
        int buf = s % STAGES;
        const char* A = Abase + (size_t)s * BK * 2;
        const char* B = Bbase + (size_t)s * BK * 2;
        uint32_t sa = base + SM_A + buf * STG_A;
        uint32_t sb = base + SM_B + buf * STG_B;
        #pragma unroll
        for (int i = 0; i < 4; i++) {            // A: 1024 16B chunks / 256 thr
            int idx = tid + i * 256;
            int row = idx >> 3, c = idx & 7;
            uint32_t off = (uint32_t)row * 128 + (uint32_t)c * 16;
            cpa16(sa + sw128(off), A + (size_t)row * (K * 2) + c * 16);
        }
        #pragma unroll
        for (int i = 0; i < 4; i++) {            // B: 1024 16B chunks
            int idx = tid + i * 256;
            int row = idx >> 3, c = idx & 7;
            uint32_t off = (uint32_t)row * 128 + (uint32_t)c * 16;
            cpa16(sb + sw128(off), B + (size_t)row * (K * 2) + c * 16);
        }
    };

    #pragma unroll
    for (int s = 0; s < STAGES - 1; s++) { load_stage(s); CP_COMMIT(); }

    // per-lane ldmatrix source rows
    // A x4: {m0-7@k0, m8-15@k0, m0-7@k8, m8-15@k8}
    int a_row_in16 = (lane & 7) + ((lane >> 3) & 1) * 8;
    int a_kh       = (lane >> 4);
    // B x4: {n0-7@k0, n0-7@k8, n8-15@k0, n8-15@k8}
    int b_row_in16 = (lane & 7) + ((lane >> 4) & 1) * 8;
    int b_kh       = (lane >> 3) & 1;

    float acc[4][4][4];                          // 64x32 per warp
    #pragma unroll
    for (int i = 0; i < 4; i++)
        #pragma unroll
        for (int j = 0; j < 4; j++)
            #pragma unroll
            for (int q = 0; q < 4; q++) acc[i][j][q] = 0.f;

    for (int ks = 0; ks < KSTAGES; ks++) {
        int buf = ks % STAGES;
        CP_WAIT1();
        __syncthreads();
        if (ks + STAGES - 1 < KSTAGES) load_stage(ks + STAGES - 1);
        CP_COMMIT();

        uint32_t sa = base + SM_A + buf * STG_A;
        uint32_t sb = base + SM_B + buf * STG_B;

        #pragma unroll
        for (int kk = 0; kk < BK / 16; kk++) {     // 4 k16 steps
            uint32_t af[4][4], bf[2][4];
            #pragma unroll
            for (int mi = 0; mi < 4; mi++) {
                uint32_t row = (uint32_t)(wm * 64 + mi * 16 + a_row_in16);
                uint32_t off = row * 128 + (uint32_t)(kk * 2 + a_kh) * 16;
                ldsm_x4(af[mi][0], af[mi][1], af[mi][2], af[mi][3],
                        sa + sw128(off));
            }
            #pragma unroll
            for (int nj = 0; nj < 2; nj++) {       // each covers n16 (2 frags)
                uint32_t row = (uint32_t)(wn * 32 + nj * 16 + b_row_in16);
                uint32_t off = row * 128 + (uint32_t)(kk * 2 + b_kh) * 16;
                ldsm_x4(bf[nj][0], bf[nj][1], bf[nj][2], bf[nj][3],
                        sb + sw128(off));
            }
            #pragma unroll
            for (int mi = 0; mi < 4; mi++)
                #pragma unroll
                for (int nj = 0; nj < 2; nj++) {
                    mma16816(acc[mi][nj * 2 + 0], af[mi], &bf[nj][0]);
                    mma16816(acc[mi][nj * 2 + 1], af[mi], &bf[nj][2]);
                }
        }
    }

    // ---- epilogue: scale + bias, direct STG.64 ----
    float oscale = (g_scl[2] * g_scl[3]) * (1.f / (448.f * 448.f));

    int mrow0 = bm * BM + wm * 64 + (lane >> 2);
    int ncol0 = bn * BN + wn * 32 + (lane & 3) * 2;

    #pragma unroll
    for (int mi = 0; mi < 4; mi++) {
        #pragma unroll
        for (int j = 0; j < 4; j++) {
            int ncol = ncol0 + j * 8;
            float2 bv = *(const float2*)&bias[ncol];
            int r0 = mrow0 + mi * 16;
            float2 v0, v1;
            v0.x = acc[mi][j][0] * oscale + bv.x;
            v0.y = acc[mi][j][1] * oscale + bv.y;
            v1.x = acc[mi][j][2] * oscale + bv.x;
            v1.y = acc[mi][j][3] * oscale + bv.y;
            *(float2*)&out[(size_t)r0 * N + ncol]       = v0;
            *(float2*)&out[(size_t)(r0 + 8) * N + ncol] = v1;
        }
    }
}

// ---------------- launch ----------------
extern "C" void kernel_launch(void* const* d_in, const int* in_sizes, int n_in,
                              void* d_out, int out_size) {
    const float* x    = (const float*)d_in[0];
    const float* w    = (const float*)d_in[1];
    const float* bias = (const float*)d_in[2];
    float* out = (float*)d_out;

    cudaFuncSetAttribute(k_gemm, cudaFuncAttributeMaxDynamicSharedMemorySize,
                         (int)SMEM_BYTES);

    k_amax_all<<<AX_BLOCKS + AW_BLOCKS, 512>>>(x, w);
    k_scale<<<1, 1024>>>();
    k_quant_all<<<QX_BLOCKS + QW_BLOCKS, 256>>>(x, w);

    int grid = (M / BM) * (N / BN);   // 64 * 128 = 8192
    k_gemm<<<grid, 256, SMEM_BYTES>>>(bias, out);
}

// round 8
// speedup vs baseline: 1.1059x; 1.0198x over previous
#include <cuda_runtime.h>
#include <cuda_bf16.h>
#include <cstdint>

// ============================================================
// FP8ProperLinear: out = fq(x) @ fq(w)^T + bias
//   fq = per-tensor fake e4m3 quantize (values have <=4-bit significands)
// Exactness: quantize in scaled space -> bf16 (exact), bf16 products are
// exact, fp32 accumulate; fold amax_x*amax_w/448^2 + bias into epilogue.
// GEMM core: mma.sync m16n8k16 bf16, CTA tile 128x128x64, 128 threads,
// warp tile 64x64 (high MMA:LDSM density), 3-stage cp.async pipeline,
// 2 CTAs/SM (independent CTAs overlap each other's sync windows).
// Pre-GEMM: fused amax (partials) -> scale -> fused quant.
// (tcgen05 unavailable: harness PTX target is plain sm_103.)
// ============================================================

static constexpr int M = 8192;     // B*S
static constexpr int N = 16384;    // OUT_F
static constexpr int K = 4096;     // IN_F

static constexpr int BM = 128, BN = 128, BK = 64;
static constexpr int STAGES = 3;
static constexpr int KSTAGES = K / BK;            // 64
static constexpr int GROUP_M = 8;
static constexpr int GTHREADS = 128;              // GEMM block size

static constexpr uint32_t STG_A = BM * BK * 2;    // 16384 B
static constexpr uint32_t STG_B = BN * BK * 2;    // 16384 B
static constexpr uint32_t SM_A = 0;
static constexpr uint32_t SM_B = STAGES * STG_A;  // 49152
static constexpr uint32_t SMEM_BYTES = SM_B + STAGES * STG_B;  // 98304 (x2 CTAs = 192K)

// amax/quant grid split
static constexpr int AX_BLOCKS = 1024;            // x amax blocks
static constexpr int AW_BLOCKS = 2048;            // w amax blocks
static constexpr int QX_BLOCKS = 2048;            // x quant blocks
static constexpr int QW_BLOCKS = 4096;            // w quant blocks

// ---------------- device scratch (no mallocs allowed) ----------------
__device__ __nv_bfloat16 g_xq[(size_t)M * K];   // 64 MiB
__device__ __nv_bfloat16 g_wq[(size_t)N * K];   // 128 MiB
__device__ float g_part[AX_BLOCKS + AW_BLOCKS]; // per-block partial maxima
__device__ float g_scl[4];                      // [0]=scale_x [1]=scale_w [2]=amax_x [3]=amax_w

// ---------------- helpers ----------------
__device__ __forceinline__ uint32_t smem_u32(const void* p) {
    uint32_t a;
    asm("{ .reg .u64 t; cvta.to.shared.u64 t, %1; cvt.u32.u64 %0, t; }" : "=r"(a) : "l"(p));
    return a;
}
__device__ __forceinline__ uint32_t sw128(uint32_t off) {   // SW128 XOR swizzle
    return off ^ ((off >> 3) & 0x70);
}
__device__ __forceinline__ void cpa16(uint32_t dst, const void* src) {
    asm volatile("cp.async.cg.shared.global [%0], [%1], 16;" :: "r"(dst), "l"(src));
}
#define CP_COMMIT() asm volatile("cp.async.commit_group;" ::: "memory")
#define CP_WAIT1()  asm volatile("cp.async.wait_group 1;" ::: "memory")

__device__ __forceinline__ void ldsm_x4(uint32_t& r0, uint32_t& r1, uint32_t& r2,
                                        uint32_t& r3, uint32_t addr) {
    asm volatile("ldmatrix.sync.aligned.m8n8.x4.shared.b16 {%0,%1,%2,%3}, [%4];"
                 : "=r"(r0), "=r"(r1), "=r"(r2), "=r"(r3) : "r"(addr));
}
__device__ __forceinline__ void mma16816(float* c, const uint32_t* a, const uint32_t* b) {
    asm volatile("mma.sync.aligned.m16n8k16.row.col.f32.bf16.bf16.f32 "
                 "{%0,%1,%2,%3}, {%4,%5,%6,%7}, {%8,%9}, {%0,%1,%2,%3};"
                 : "+f"(c[0]), "+f"(c[1]), "+f"(c[2]), "+f"(c[3])
                 : "r"(a[0]), "r"(a[1]), "r"(a[2]), "r"(a[3]), "r"(b[0]), "r"(b[1]));
}

// ---------------- fake e4m3 quantize (scaled space; exact exponent) ----------------
__device__ __forceinline__ float fq_scaled(float v, float scale) {
    float c = fminf(fmaxf(v, -448.f), 448.f);
    float s = c * scale;
    float mag = fmaxf(fabsf(s), 1e-12f);                 // always normal
    uint32_t e = (__float_as_uint(mag) >> 23) & 0xFFu;   // biased exponent
    float step = __uint_as_float((e - 3u) << 23);        // 2^(e-127)/8 (exact)
    float inv  = __uint_as_float((257u - e) << 23);      // 1/step      (exact)
    float r = rintf(mag * inv);                          // round-half-even
    float q = r * step;                                  // <=5 sig bits: exact
    return (s > 0.f) ? q : ((s < 0.f) ? -q : 0.f);
}

// ---------------- pre-GEMM kernels ----------------
__global__ void __launch_bounds__(512)
k_amax_all(const float* __restrict__ x, const float* __restrict__ w) {
    __shared__ float red[16];
    int bid = blockIdx.x;
    const float4* p4;
    int n4, b0, nb;
    if (bid < AX_BLOCKS) { p4 = (const float4*)x; n4 = (M * K) / 4; b0 = bid;             nb = AX_BLOCKS; }
    else                 { p4 = (const float4*)w; n4 = (N * K) / 4; b0 = bid - AX_BLOCKS; nb = AW_BLOCKS; }

    float m0 = 0.f, m1 = 0.f;
    int stride = nb * 512 * 2;
    int i0 = (b0 * 512 + threadIdx.x) * 2;
    for (int i = i0; i < n4; i += stride) {
        float4 v = p4[i];
        m0 = fmaxf(m0, fmaxf(fmaxf(fabsf(v.x), fabsf(v.y)), fmaxf(fabsf(v.z), fabsf(v.w))));
        if (i + 1 < n4) {
            float4 u = p4[i + 1];
            m1 = fmaxf(m1, fmaxf(fmaxf(fabsf(u.x), fabsf(u.y)), fmaxf(fabsf(u.z), fabsf(u.w))));
        }
    }
    float m = fmaxf(m0, m1);
    #pragma unroll
    for (int o = 16; o; o >>= 1) m = fmaxf(m, __shfl_xor_sync(0xffffffffu, m, o));
    if ((threadIdx.x & 31) == 0) red[threadIdx.x >> 5] = m;
    __syncthreads();
    if (threadIdx.x < 32) {
        float t = (threadIdx.x < 16) ? red[threadIdx.x] : 0.f;
        #pragma unroll
        for (int o = 8; o; o >>= 1) t = fmaxf(t, __shfl_xor_sync(0xffffffffu, t, o));
        if (threadIdx.x == 0) g_part[bid] = fminf(t, 448.f);  // amax of clamped tensor
    }
}

__global__ void __launch_bounds__(1024) k_scale() {
    __shared__ float red[32];
    int t = threadIdx.x;
    float mx = (t < AX_BLOCKS) ? g_part[t] : 0.f;
    float mw = fmaxf(g_part[AX_BLOCKS + t], g_part[AX_BLOCKS + 1024 + t]);
    #pragma unroll
    for (int o = 16; o; o >>= 1) {
        mx = fmaxf(mx, __shfl_xor_sync(0xffffffffu, mx, o));
        mw = fmaxf(mw, __shfl_xor_sync(0xffffffffu, mw, o));
    }
    if ((t & 31) == 0) red[t >> 5] = mx;
    __syncthreads();
    if (t < 32) {
        float v = red[t];
        #pragma unroll
        for (int o = 16; o; o >>= 1) v = fmaxf(v, __shfl_xor_sync(0xffffffffu, v, o));
        if (t == 0) {
            float ax = fmaxf(v, 1e-12f);
            g_scl[0] = 448.f / ax;
            g_scl[2] = ax;
        }
    }
    __syncthreads();
    if ((t & 31) == 0) red[t >> 5] = mw;
    __syncthreads();
    if (t < 32) {
        float v = red[t];
        #pragma unroll
        for (int o = 16; o; o >>= 1) v = fmaxf(v, __shfl_xor_sync(0xffffffffu, v, o));
        if (t == 0) {
            float aw = fmaxf(v, 1e-12f);
            g_scl[1] = 448.f / aw;
            g_scl[3] = aw;
        }
    }
}

__global__ void __launch_bounds__(256)
k_quant_all(const float* __restrict__ x, const float* __restrict__ w) {
    int bid = blockIdx.x;
    const float4* p4;
    uint2* o4;
    float scale;
    int n4, b0, nb;
    if (bid < QX_BLOCKS) {
        p4 = (const float4*)x; o4 = (uint2*)g_xq; scale = g_scl[0];
        n4 = (M * K) / 4; b0 = bid; nb = QX_BLOCKS;
    } else {
        p4 = (const float4*)w; o4 = (uint2*)g_wq; scale = g_scl[1];
        n4 = (N * K) / 4; b0 = bid - QX_BLOCKS; nb = QW_BLOCKS;
    }
    int stride = nb * 256 * 2;
    int i0 = (b0 * 256 + threadIdx.x) * 2;
    for (int i = i0; i < n4; i += stride) {
        float4 v = p4[i];
        bool has2 = (i + 1) < n4;
        float4 u = has2 ? p4[i + 1] : v;
        unsigned short b0s = __bfloat16_as_ushort(__float2bfloat16(fq_scaled(v.x, scale)));
        unsigned short b1s = __bfloat16_as_ushort(__float2bfloat16(fq_scaled(v.y, scale)));
        unsigned short b2s = __bfloat16_as_ushort(__float2bfloat16(fq_scaled(v.z, scale)));
        unsigned short b3s = __bfloat16_as_ushort(__float2bfloat16(fq_scaled(v.w, scale)));
        uint2 r;
        r.x = (uint32_t)b0s | ((uint32_t)b1s << 16);
        r.y = (uint32_t)b2s | ((uint32_t)b3s << 16);
        o4[i] = r;
        if (has2) {
            unsigned short c0 = __bfloat16_as_ushort(__float2bfloat16(fq_scaled(u.x, scale)));
            unsigned short c1 = __bfloat16_as_ushort(__float2bfloat16(fq_scaled(u.y, scale)));
            unsigned short c2 = __bfloat16_as_ushort(__float2bfloat16(fq_scaled(u.z, scale)));
            unsigned short c3 = __bfloat16_as_ushort(__float2bfloat16(fq_scaled(u.w, scale)));
            uint2 r2;
            r2.x = (uint32_t)c0 | ((uint32_t)c1 << 16);
            r2.y = (uint32_t)c2 | ((uint32_t)c3 << 16);
            o4[i + 1] = r2;
        }
    }
}

// ---------------- GEMM: out = (xq @ wq^T) * oscale + bias ----------------
__global__ void __launch_bounds__(GTHREADS, 2)
k_gemm(const float* __restrict__ bias, float* __restrict__ out) {
    extern __shared__ __align__(128) char smem[];
    const uint32_t base = smem_u32(smem);
    const int tid  = threadIdx.x;
    const int wid  = tid >> 5, lane = tid & 31;
    const int wm   = wid & 1;      // 2 warps along M: rows wm*64..+63
    const int wn   = wid >> 1;     // 2 warps along N: cols wn*64..+63

    // grouped raster
    const int num_pid_n = N / BN;                 // 128
    int pid = blockIdx.x;
    int group_sz = GROUP_M * num_pid_n;           // 1024
    int g = pid / group_sz;
    int pin = pid - g * group_sz;
    int bm = g * GROUP_M + (pin % GROUP_M);
    int bn = pin / GROUP_M;

    const char* Abase = (const char*)(g_xq + (size_t)bm * BM * K);
    const char* Bbase = (const char*)(g_wq + (size_t)bn * BN * K);

    // ---- stage loader: A 128x64 bf16 (16KB), B 128x64 bf16 (16KB), SW128 ----
    auto load_stage = [&](int s) {
        int buf = s % STAGES;
        const char* A = Abase + (size_t)s * BK * 2;
        const char* B = Bbase + (size_t)s * BK * 2;
        uint32_t sa = base + SM_A + buf * STG_A;
        uint32_t sb = base + SM_B + buf * STG_B;
        #pragma unroll
        for (int i = 0; i < 8; i++) {            // A: 1024 16B chunks / 128 thr
            int idx = tid + i * GTHREADS;
            int row = idx >> 3, c = idx & 7;
            uint32_t off = (uint32_t)row * 128 + (uint32_t)c * 16;
            cpa16(sa + sw128(off), A + (size_t)row * (K * 2) + c * 16);
        }
        #pragma unroll
        for (int i = 0; i < 8; i++) {            // B: 1024 16B chunks
            int idx = tid + i * GTHREADS;
            int row = idx >> 3, c = idx & 7;
            uint32_t off = (uint32_t)row * 128 + (uint32_t)c * 16;
            cpa16(sb + sw128(off), B + (size_t)row * (K * 2) + c * 16);
        }
    };

    #pragma unroll
    for (int s = 0; s < STAGES - 1; s++) { load_stage(s); CP_COMMIT(); }

    // per-lane ldmatrix source rows
    // A x4: {m0-7@k0, m8-15@k0, m0-7@k8, m8-15@k8}
    int a_row_in16 = (lane & 7) + ((lane >> 3) & 1) * 8;
    int a_kh       = (lane >> 4);
    // B x4: {n0-7@k0, n0-7@k8, n8-15@k0, n8-15@k8}
    int b_row_in16 = (lane & 7) + ((lane >> 4) & 1) * 8;
    int b_kh       = (lane >> 3) & 1;

    float acc[4][8][4];                          // 64x64 per warp
    #pragma unroll
    for (int i = 0; i < 4; i++)
        #pragma unroll
        for (int j = 0; j < 8; j++)
            #pragma unroll
            for (int q = 0; q < 4; q++) acc[i][j][q] = 0.f;

    for (int ks = 0; ks < KSTAGES; ks++) {
        int buf = ks % STAGES;
        CP_WAIT1();
        __syncthreads();
        if (ks + STAGES - 1 < KSTAGES) load_stage(ks + STAGES - 1);
        CP_COMMIT();

        uint32_t sa = base + SM_A + buf * STG_A;
        uint32_t sb = base + SM_B + buf * STG_B;

        #pragma unroll
        for (int kk = 0; kk < BK / 16; kk++) {     // 4 k16 steps
            uint32_t af[4][4], bf[4][4];
            #pragma unroll
            for (int mi = 0; mi < 4; mi++) {
                uint32_t row = (uint32_t)(wm * 64 + mi * 16 + a_row_in16);
                uint32_t off = row * 128 + (uint32_t)(kk * 2 + a_kh) * 16;
                ldsm_x4(af[mi][0], af[mi][1], af[mi][2], af[mi][3],
                        sa + sw128(off));
            }
            #pragma unroll
            for (int nj = 0; nj < 4; nj++) {       // each covers n16 (2 frags)
                uint32_t row = (uint32_t)(wn * 64 + nj * 16 + b_row_in16);
                uint32_t off = row * 128 + (uint32_t)(kk * 2 + b_kh) * 16;
                ldsm_x4(bf[nj][0], bf[nj][1], bf[nj][2], bf[nj][3],
                        sb + sw128(off));
            }
            #pragma unroll
            for (int mi = 0; mi < 4; mi++)
                #pragma unroll
                for (int nj = 0; nj < 4; nj++) {
                    mma16816(acc[mi][nj * 2 + 0], af[mi], &bf[nj][0]);
                    mma16816(acc[mi][nj * 2 + 1], af[mi], &bf[nj][2]);
                }
        }
    }

    // ---- epilogue: scale + bias, direct STG.64 ----
    float oscale = (g_scl[2] * g_scl[3]) * (1.f / (448.f * 448.f));

    int mrow0 = bm * BM + wm * 64 + (lane >> 2);
    int ncol0 = bn * BN + wn * 64 + (lane & 3) * 2;

    #pragma unroll
    for (int mi = 0; mi < 4; mi++) {
        #pragma unroll
        for (int j = 0; j < 8; j++) {
            int ncol = ncol0 + j * 8;
            float2 bv = *(const float2*)&bias[ncol];
            int r0 = mrow0 + mi * 16;
            float2 v0, v1;
            v0.x = acc[mi][j][0] * oscale + bv.x;
            v0.y = acc[mi][j][1] * oscale + bv.y;
            v1.x = acc[mi][j][2] * oscale + bv.x;
            v1.y = acc[mi][j][3] * oscale + bv.y;
            *(float2*)&out[(size_t)r0 * N + ncol]       = v0;
            *(float2*)&out[(size_t)(r0 + 8) * N + ncol] = v1;
        }
    }
}

// ---------------- launch ----------------
extern "C" void kernel_launch(void* const* d_in, const int* in_sizes, int n_in,
                              void* d_out, int out_size) {
    const float* x    = (const float*)d_in[0];
    const float* w    = (const float*)d_in[1];
    const float* bias = (const float*)d_in[2];
    float* out = (float*)d_out;

    cudaFuncSetAttribute(k_gemm, cudaFuncAttributeMaxDynamicSharedMemorySize,
                         (int)SMEM_BYTES);

    k_amax_all<<<AX_BLOCKS + AW_BLOCKS, 512>>>(x, w);
    k_scale<<<1, 1024>>>();
    k_quant_all<<<QX_BLOCKS + QW_BLOCKS, 256>>>(x, w);

    int grid = (M / BM) * (N / BN);   // 64 * 128 = 8192
    k_gemm<<<grid, GTHREADS, SMEM_BYTES>>>(bias, out);
}